// round 3
// baseline (speedup 1.0000x reference)
#include <cuda_runtime.h>
#include <cuda_bf16.h>
#include <cstdint>

#define B_   64
#define TQ_  2048
#define TK_  2048
#define D_   64

// Scratch: per-row 1/rowsum (pass1 -> pass2). Static device array (no allocation).
__device__ float g_rowinv[B_ * TQ_];
// Mask element kind: 1 = 1-byte elements (bool/uint8), 0 = 4-byte elements (int32/float32)
__device__ int g_mask_kind;

// ---------------------------------------------------------------------------
// Mask dtype detector: reads first 4096 bytes. If every 32-bit word is in
// {0, 1, 0x3F800000} the buffer is 4-byte elements (int32 0/1 or float 0/1).
// A byte-mask (random 0/1 bytes) violates that almost surely.
// ---------------------------------------------------------------------------
__global__ void detect_mask_kind(const unsigned char* __restrict__ m) {
    __shared__ int flag;
    int tid = threadIdx.x;
    if (tid == 0) flag = 0;
    __syncthreads();
    const uint4* m4 = (const uint4*)m;
    uint4 u = m4[tid];  // 256 threads * 16B = 4096 bytes
    unsigned w[4] = {u.x, u.y, u.z, u.w};
    int bad = 0;
#pragma unroll
    for (int i = 0; i < 4; i++) {
        unsigned x = w[i];
        if (!(x == 0u || x == 1u || x == 0x3F800000u)) bad = 1;
    }
    if (bad) atomicOr(&flag, 1);
    __syncthreads();
    if (tid == 0) g_mask_kind = flag ? 1 : 0;  // bad word => byte mask
}

// ---------------------------------------------------------------------------
// fast exp(s/8) via exp2: 5th-order poly, rel err ~3e-6. Valid |s| < ~600.
// ---------------------------------------------------------------------------
__device__ __forceinline__ float fexp8(float s) {
    const float C = 0.18033688011112042f;  // log2(e)/8
    float z = fmaf(s, C, 12582912.0f);     // magic: 1.5*2^23
    float nf = z - 12582912.0f;
    float f = fmaf(s, C, -nf);             // f in [-0.5, 0.5]
    int n = __float_as_int(z) - 0x4B400000;
    float p = 1.3333558146e-3f;
    p = fmaf(p, f, 9.6181291076e-3f);
    p = fmaf(p, f, 5.5504108665e-2f);
    p = fmaf(p, f, 2.4022650696e-1f);
    p = fmaf(p, f, 6.9314718056e-1f);
    p = fmaf(p, f, 1.0f);
    return __int_as_float(__float_as_int(p) + (n << 23));
}

__device__ __forceinline__ unsigned cvt_tf32(float x) {
    unsigned r;
    asm("cvt.rna.tf32.f32 %0, %1;" : "=r"(r) : "f"(x));
    return r;
}

__device__ __forceinline__ void mma8(float c[4], const unsigned a[4],
                                     unsigned b0, unsigned b1) {
    asm("mma.sync.aligned.m16n8k8.row.col.f32.tf32.tf32.f32 "
        "{%0,%1,%2,%3}, {%4,%5,%6,%7}, {%8,%9}, {%0,%1,%2,%3};"
        : "+f"(c[0]), "+f"(c[1]), "+f"(c[2]), "+f"(c[3])
        : "r"(a[0]), "r"(a[1]), "r"(a[2]), "r"(a[3]), "r"(b0), "r"(b1));
}

// ---------------------------------------------------------------------------
// Main pass. PHASE2=false: compute rowsums -> g_rowinv.
//            PHASE2=true : recompute S, write normalized attn, accumulate O.
// CTA: 64 q-rows x full TK. 8 warps: rowgroup=wid/2 (16 rows), keygroup=wid&1.
// ---------------------------------------------------------------------------
template <bool PHASE2>
__global__ __launch_bounds__(256, 2)
void attn_pass(const float* __restrict__ q, const float* __restrict__ k,
               const float* __restrict__ v, const unsigned char* __restrict__ mask,
               float* __restrict__ out, float* __restrict__ attn) {
    __shared__ float Ks[64][68];                    // K tile; reused as V tile
    __shared__ float Ps[64][68];                    // unnormalized probs (phase2)
    __shared__ __align__(16) unsigned char Ms[64 * 80];  // mask tile, stride 80
    __shared__ float RowRed[64];                    // rowsum (p1) / rowinv (p2)

    const int tid = threadIdx.x;
    const int wid = tid >> 5;
    const int lane = tid & 31;
    const int bb = blockIdx.y;
    const int qbase = blockIdx.x * 64;

    const float* qp = q + ((size_t)bb * TQ_ + qbase) * D_;
    const float* kp = k + (size_t)bb * TK_ * D_;
    const float* vp = v + (size_t)bb * TK_ * D_;
    const size_t mbase = ((size_t)bb * TQ_ + qbase) * TK_;
    const int mask_is_byte = g_mask_kind;

    if (tid < 64)
        RowRed[tid] = PHASE2 ? g_rowinv[bb * TQ_ + qbase + tid] : 0.0f;

    // Stage Q (64x64 f32) into Ks temporarily
#pragma unroll
    for (int j = 0; j < 4; j++) {
        int i = tid + j * 256;
        int r = i >> 4, c4 = (i & 15) * 4;
        *(float4*)&Ks[r][c4] = *(const float4*)(qp + r * D_ + c4);
    }
    __syncthreads();

    const int rg = wid >> 1;       // row group (16 rows)
    const int kg = wid & 1;        // key/d group (32 cols)
    const int r0 = rg * 16 + (lane >> 2);
    const int qc = lane & 3;

    // Q fragments (A of m16n8k8), kept in registers for the whole kernel
    unsigned qa[8][4];
#pragma unroll
    for (int kc = 0; kc < 8; kc++) {
        qa[kc][0] = cvt_tf32(Ks[r0][kc * 8 + qc]);
        qa[kc][1] = cvt_tf32(Ks[r0 + 8][kc * 8 + qc]);
        qa[kc][2] = cvt_tf32(Ks[r0][kc * 8 + qc + 4]);
        qa[kc][3] = cvt_tf32(Ks[r0 + 8][kc * 8 + qc + 4]);
    }
    __syncthreads();

    float oacc[4][4];
    if (PHASE2) {
#pragma unroll
        for (int nt = 0; nt < 4; nt++)
#pragma unroll
            for (int i = 0; i < 4; i++) oacc[nt][i] = 0.0f;
    }
    float rs0 = 0.0f, rs1 = 0.0f;

    for (int kt = 0; kt < TK_ / 64; kt++) {
        const int kb = kt * 64;

        // Stage K tile (64 keys x 64 d)
#pragma unroll
        for (int j = 0; j < 4; j++) {
            int i = tid + j * 256;
            int r = i >> 4, c4 = (i & 15) * 4;
            *(float4*)&Ks[r][c4] = *(const float4*)(kp + (size_t)(kb + r) * D_ + c4);
        }
        // Stage mask tile (64 q-rows x 64 keys) into bytes
        if (mask_is_byte) {
            int r = tid >> 2, seg = (tid & 3) * 16;
            *(uint4*)&Ms[r * 80 + seg] =
                *(const uint4*)(mask + mbase + (size_t)r * TK_ + kb + seg);
        } else {
            const int* mi = (const int*)mask;
#pragma unroll
            for (int j = 0; j < 4; j++) {
                int i4 = tid + j * 256;  // int4 index (1024 total)
                int r = i4 >> 4, c4 = (i4 & 15) * 4;
                int4 mm = *(const int4*)(mi + mbase + (size_t)r * TK_ + kb + c4);
                uchar4 pk;
                pk.x = mm.x ? 1 : 0; pk.y = mm.y ? 1 : 0;
                pk.z = mm.z ? 1 : 0; pk.w = mm.w ? 1 : 0;
                *(uchar4*)&Ms[r * 80 + c4] = pk;
            }
        }
        __syncthreads();

        // S = Q * K^T for this warp's 16x32 subtile
        float c[4][4];
#pragma unroll
        for (int nt = 0; nt < 4; nt++)
#pragma unroll
            for (int i = 0; i < 4; i++) c[nt][i] = 0.0f;

#pragma unroll
        for (int kc = 0; kc < 8; kc++) {
#pragma unroll
            for (int nt = 0; nt < 4; nt++) {
                int key = kg * 32 + nt * 8 + (lane >> 2);
                unsigned b0 = cvt_tf32(Ks[key][kc * 8 + qc]);
                unsigned b1 = cvt_tf32(Ks[key][kc * 8 + qc + 4]);
                mma8(c[nt], qa[kc], b0, b1);
            }
        }

        // mask + exp (+ attn write / Ps store / rowsum)
#pragma unroll
        for (int nt = 0; nt < 4; nt++) {
            int col = kg * 32 + nt * 8 + 2 * qc;
            float e00 = Ms[r0 * 80 + col]       ? 0.0f : fexp8(c[nt][0]);
            float e01 = Ms[r0 * 80 + col + 1]   ? 0.0f : fexp8(c[nt][1]);
            float e10 = Ms[(r0 + 8) * 80 + col] ? 0.0f : fexp8(c[nt][2]);
            float e11 = Ms[(r0 + 8) * 80 + col + 1] ? 0.0f : fexp8(c[nt][3]);
            if (PHASE2) {
                float inv0 = RowRed[r0];
                float inv1 = RowRed[r0 + 8];
                size_t ai = ((size_t)(bb * TQ_ + qbase + r0)) * TK_ + kb + col;
                *(float2*)(attn + ai) = make_float2(e00 * inv0, e01 * inv0);
                *(float2*)(attn + ai + (size_t)8 * TK_) =
                    make_float2(e10 * inv1, e11 * inv1);
                *(float2*)&Ps[r0][col] = make_float2(e00, e01);
                *(float2*)&Ps[r0 + 8][col] = make_float2(e10, e11);
            } else {
                rs0 += e00 + e01;
                rs1 += e10 + e11;
            }
        }

        if (PHASE2) {
            __syncthreads();  // Ps complete; Ks (K tile) dead
            // Stage V tile into Ks
#pragma unroll
            for (int j = 0; j < 4; j++) {
                int i = tid + j * 256;
                int r = i >> 4, c4 = (i & 15) * 4;
                *(float4*)&Ks[r][c4] =
                    *(const float4*)(vp + (size_t)(kb + r) * D_ + c4);
            }
            __syncthreads();

            // O += P * V : warp does O rows rg*16..+16, d-cols kg*32..+32
#pragma unroll
            for (int kc = 0; kc < 8; kc++) {
                unsigned a[4];
                a[0] = cvt_tf32(Ps[r0][kc * 8 + qc]);
                a[1] = cvt_tf32(Ps[r0 + 8][kc * 8 + qc]);
                a[2] = cvt_tf32(Ps[r0][kc * 8 + qc + 4]);
                a[3] = cvt_tf32(Ps[r0 + 8][kc * 8 + qc + 4]);
#pragma unroll
                for (int nt = 0; nt < 4; nt++) {
                    int dcol = kg * 32 + nt * 8 + (lane >> 2);
                    unsigned b0 = cvt_tf32(Ks[kc * 8 + qc][dcol]);
                    unsigned b1 = cvt_tf32(Ks[kc * 8 + qc + 4][dcol]);
                    mma8(oacc[nt], a, b0, b1);
                }
            }
        }
        __syncthreads();  // everyone done with Ks/Ms/Ps before next tile
    }

    if (PHASE2) {
        float inv0 = RowRed[r0];
        float inv1 = RowRed[r0 + 8];
#pragma unroll
        for (int nt = 0; nt < 4; nt++) {
            int dcol = kg * 32 + nt * 8 + 2 * qc;
            size_t oi = ((size_t)(bb * TQ_ + qbase + r0)) * D_ + dcol;
            *(float2*)(out + oi) =
                make_float2(oacc[nt][0] * inv0, oacc[nt][1] * inv0);
            *(float2*)(out + oi + (size_t)8 * D_) =
                make_float2(oacc[nt][2] * inv1, oacc[nt][3] * inv1);
        }
    } else {
        // reduce rowsums: across lane%4 quads, then across the 2 key-group warps
        rs0 += __shfl_xor_sync(0xFFFFFFFFu, rs0, 1);
        rs0 += __shfl_xor_sync(0xFFFFFFFFu, rs0, 2);
        rs1 += __shfl_xor_sync(0xFFFFFFFFu, rs1, 1);
        rs1 += __shfl_xor_sync(0xFFFFFFFFu, rs1, 2);
        if (qc == 0) {
            atomicAdd(&RowRed[r0], rs0);
            atomicAdd(&RowRed[r0 + 8], rs1);
        }
        __syncthreads();
        if (tid < 64)
            g_rowinv[bb * TQ_ + qbase + tid] = 1.0f / RowRed[tid];
    }
}

extern "C" void kernel_launch(void* const* d_in, const int* in_sizes, int n_in,
                              void* d_out, int out_size) {
    const float* q = (const float*)d_in[0];
    const float* k = (const float*)d_in[1];
    const float* v = (const float*)d_in[2];
    const unsigned char* mask = (const unsigned char*)d_in[3];

    float* out = (float*)d_out;                       // [B, TQ, D]
    float* attn = out + (size_t)B_ * TQ_ * D_;        // [B, TQ, TK]

    detect_mask_kind<<<1, 256>>>(mask);

    dim3 grid(TQ_ / 64, B_);
    attn_pass<false><<<grid, 256>>>(q, k, v, mask, out, attn);
    attn_pass<true><<<grid, 256>>>(q, k, v, mask, out, attn);
}

// round 5
// speedup vs baseline: 1.0458x; 1.0458x over previous
#include <cuda_runtime.h>
#include <cuda_bf16.h>
#include <cstdint>

#define B_   64
#define TQ_  2048
#define TK_  2048
#define D_   64

// Mask element kind: 1 = 1-byte elements (bool/uint8), 0 = 4-byte elements (int32/float32)
__device__ int g_mask_kind;

// ---------------------------------------------------------------------------
// Mask dtype detector: reads first 4096 bytes. If every 32-bit word is in
// {0, 1, 0x3F800000} the buffer is 4-byte elements (int32 0/1 or float 0/1).
// A byte-mask (random 0/1 bytes) violates that almost surely.
// ---------------------------------------------------------------------------
__global__ void detect_mask_kind(const unsigned char* __restrict__ m) {
    __shared__ int flag;
    int tid = threadIdx.x;
    if (tid == 0) flag = 0;
    __syncthreads();
    const uint4* m4 = (const uint4*)m;
    uint4 u = m4[tid];  // 256 threads * 16B = 4096 bytes
    unsigned w[4] = {u.x, u.y, u.z, u.w};
    int bad = 0;
#pragma unroll
    for (int i = 0; i < 4; i++) {
        unsigned x = w[i];
        if (!(x == 0u || x == 1u || x == 0x3F800000u)) bad = 1;
    }
    if (bad) atomicOr(&flag, 1);
    __syncthreads();
    if (tid == 0) g_mask_kind = flag ? 1 : 0;  // bad word => byte mask
}

// ---------------------------------------------------------------------------
// fast exp(s/8) via exp2: 5th-order poly, rel err ~3e-6. Valid |s| < ~600.
// ---------------------------------------------------------------------------
__device__ __forceinline__ float fexp8(float s) {
    const float C = 0.18033688011112042f;  // log2(e)/8
    float z = fmaf(s, C, 12582912.0f);     // magic: 1.5*2^23
    float nf = z - 12582912.0f;
    float f = fmaf(s, C, -nf);             // f in [-0.5, 0.5]
    int n = __float_as_int(z) - 0x4B400000;
    float p = 1.3333558146e-3f;
    p = fmaf(p, f, 9.6181291076e-3f);
    p = fmaf(p, f, 5.5504108665e-2f);
    p = fmaf(p, f, 2.4022650696e-1f);
    p = fmaf(p, f, 6.9314718056e-1f);
    p = fmaf(p, f, 1.0f);
    return __int_as_float(__float_as_int(p) + (n << 23));
}

__device__ __forceinline__ unsigned cvt_tf32(float x) {
    unsigned r;
    asm("cvt.rna.tf32.f32 %0, %1;" : "=r"(r) : "f"(x));
    return r;
}

__device__ __forceinline__ void mma8(float c[4], const unsigned a[4],
                                     unsigned b0, unsigned b1) {
    asm("mma.sync.aligned.m16n8k8.row.col.f32.tf32.tf32.f32 "
        "{%0,%1,%2,%3}, {%4,%5,%6,%7}, {%8,%9}, {%0,%1,%2,%3};"
        : "+f"(c[0]), "+f"(c[1]), "+f"(c[2]), "+f"(c[3])
        : "r"(a[0]), "r"(a[1]), "r"(a[2]), "r"(a[3]), "r"(b0), "r"(b1));
}

// ---------------------------------------------------------------------------
// Fused single pass. CTA: 64 q-rows x full TK. 8 warps:
// rowgroup = wid/2 (16 rows), keygroup/dgroup = wid&1 (32 cols).
// Loop: stage K+mask -> QK mma -> exp -> store unnormalized e to attn gmem,
// cvt'd e to Ps, rowsum in regs -> stage V -> PV mma (unnormalized accum).
// Tail: reduce rowsums -> inv, write scaled O, rescale own attn slice in
// place (L2-resident).
// ---------------------------------------------------------------------------
__global__ __launch_bounds__(256, 2)
void attn_fused(const float* __restrict__ q, const float* __restrict__ k,
                const float* __restrict__ v, const unsigned char* __restrict__ mask,
                float* __restrict__ out, float* __restrict__ attn) {
    __shared__ unsigned Ks[64][68];                 // tf32 bits: Q@init, then K/V tile
    __shared__ unsigned Ps[64][68];                 // tf32 bits of unnormalized probs
    __shared__ __align__(16) unsigned char Ms[64 * 80];  // mask tile, stride 80
    __shared__ float RowRed[64];                    // rowsum -> rowinv

    const int tid = threadIdx.x;
    const int wid = tid >> 5;
    const int lane = tid & 31;
    const int bb = blockIdx.y;
    const int qbase = blockIdx.x * 64;

    const float* qp = q + ((size_t)bb * TQ_ + qbase) * D_;
    const float* kp = k + (size_t)bb * TK_ * D_;
    const float* vp = v + (size_t)bb * TK_ * D_;
    float* arow = attn + ((size_t)bb * TQ_ + qbase) * TK_;
    const size_t mbase = ((size_t)bb * TQ_ + qbase) * TK_;
    const int mask_is_byte = g_mask_kind;

    if (tid < 64) RowRed[tid] = 0.0f;

    // Stage Q (64x64) into Ks, tf32-converted at staging
#pragma unroll
    for (int j = 0; j < 4; j++) {
        int i = tid + j * 256;
        int r = i >> 4, c4 = (i & 15) * 4;
        float4 x = *(const float4*)(qp + r * D_ + c4);
        uint4 u = make_uint4(cvt_tf32(x.x), cvt_tf32(x.y), cvt_tf32(x.z), cvt_tf32(x.w));
        *(uint4*)&Ks[r][c4] = u;
    }
    __syncthreads();

    const int rg = wid >> 1;       // row group (16 rows)
    const int kg = wid & 1;        // key/d group (32 cols)
    const int r0 = rg * 16 + (lane >> 2);
    const int qc = lane & 3;

    // Q fragments (A of m16n8k8), kept in registers for the whole kernel
    unsigned qa[8][4];
#pragma unroll
    for (int kc = 0; kc < 8; kc++) {
        qa[kc][0] = Ks[r0][kc * 8 + qc];
        qa[kc][1] = Ks[r0 + 8][kc * 8 + qc];
        qa[kc][2] = Ks[r0][kc * 8 + qc + 4];
        qa[kc][3] = Ks[r0 + 8][kc * 8 + qc + 4];
    }
    __syncthreads();

    float oacc[4][4];
#pragma unroll
    for (int nt = 0; nt < 4; nt++)
#pragma unroll
        for (int i = 0; i < 4; i++) oacc[nt][i] = 0.0f;
    float rs0 = 0.0f, rs1 = 0.0f;

    for (int kt = 0; kt < TK_ / 64; kt++) {
        const int kb = kt * 64;

        // Stage K tile (64 keys x 64 d), tf32-converted
#pragma unroll
        for (int j = 0; j < 4; j++) {
            int i = tid + j * 256;
            int r = i >> 4, c4 = (i & 15) * 4;
            float4 x = *(const float4*)(kp + (size_t)(kb + r) * D_ + c4);
            *(uint4*)&Ks[r][c4] =
                make_uint4(cvt_tf32(x.x), cvt_tf32(x.y), cvt_tf32(x.z), cvt_tf32(x.w));
        }
        // Stage mask tile (64 q-rows x 64 keys) as bytes
        if (mask_is_byte) {
            int r = tid >> 2, seg = (tid & 3) * 16;
            *(uint4*)&Ms[r * 80 + seg] =
                *(const uint4*)(mask + mbase + (size_t)r * TK_ + kb + seg);
        } else {
            const int* mi = (const int*)mask;
#pragma unroll
            for (int j = 0; j < 4; j++) {
                int i4 = tid + j * 256;  // int4 index (1024 total)
                int r = i4 >> 4, c4 = (i4 & 15) * 4;
                int4 mm = *(const int4*)(mi + mbase + (size_t)r * TK_ + kb + c4);
                uchar4 pk;
                pk.x = mm.x ? 1 : 0; pk.y = mm.y ? 1 : 0;
                pk.z = mm.z ? 1 : 0; pk.w = mm.w ? 1 : 0;
                *(uchar4*)&Ms[r * 80 + c4] = pk;
            }
        }
        __syncthreads();

        // S = Q * K^T for this warp's 16x32 subtile
        float c[4][4];
#pragma unroll
        for (int nt = 0; nt < 4; nt++)
#pragma unroll
            for (int i = 0; i < 4; i++) c[nt][i] = 0.0f;

#pragma unroll
        for (int kc = 0; kc < 8; kc++) {
#pragma unroll
            for (int nt = 0; nt < 4; nt++) {
                int key = kg * 32 + nt * 8 + (lane >> 2);
                mma8(c[nt], qa[kc], Ks[key][kc * 8 + qc], Ks[key][kc * 8 + qc + 4]);
            }
        }

        // mask + exp; write unnormalized e to attn gmem, cvt'd e to Ps,
        // accumulate rowsums in registers
#pragma unroll
        for (int nt = 0; nt < 4; nt++) {
            int col = kg * 32 + nt * 8 + 2 * qc;
            float e00 = Ms[r0 * 80 + col]           ? 0.0f : fexp8(c[nt][0]);
            float e01 = Ms[r0 * 80 + col + 1]       ? 0.0f : fexp8(c[nt][1]);
            float e10 = Ms[(r0 + 8) * 80 + col]     ? 0.0f : fexp8(c[nt][2]);
            float e11 = Ms[(r0 + 8) * 80 + col + 1] ? 0.0f : fexp8(c[nt][3]);
            size_t ai = (size_t)r0 * TK_ + kb + col;
            *(float2*)(arow + ai) = make_float2(e00, e01);
            *(float2*)(arow + ai + (size_t)8 * TK_) = make_float2(e10, e11);
            *(uint2*)&Ps[r0][col] = make_uint2(cvt_tf32(e00), cvt_tf32(e01));
            *(uint2*)&Ps[r0 + 8][col] = make_uint2(cvt_tf32(e10), cvt_tf32(e11));
            rs0 += e00 + e01;
            rs1 += e10 + e11;
        }

        __syncthreads();  // Ps complete; Ks (K tile) dead
        // Stage V tile into Ks, tf32-converted
#pragma unroll
        for (int j = 0; j < 4; j++) {
            int i = tid + j * 256;
            int r = i >> 4, c4 = (i & 15) * 4;
            float4 x = *(const float4*)(vp + (size_t)(kb + r) * D_ + c4);
            *(uint4*)&Ks[r][c4] =
                make_uint4(cvt_tf32(x.x), cvt_tf32(x.y), cvt_tf32(x.z), cvt_tf32(x.w));
        }
        __syncthreads();

        // O += P * V (unnormalized): warp does O rows rg*16..+16, d kg*32..+32
#pragma unroll
        for (int kc = 0; kc < 8; kc++) {
            unsigned a[4];
            a[0] = Ps[r0][kc * 8 + qc];
            a[1] = Ps[r0 + 8][kc * 8 + qc];
            a[2] = Ps[r0][kc * 8 + qc + 4];
            a[3] = Ps[r0 + 8][kc * 8 + qc + 4];
#pragma unroll
            for (int nt = 0; nt < 4; nt++) {
                int dcol = kg * 32 + nt * 8 + (lane >> 2);
                mma8(oacc[nt], a, Ks[kc * 8 + qc][dcol], Ks[kc * 8 + qc + 4][dcol]);
            }
        }
        __syncthreads();  // everyone done with Ks/Ms/Ps before next tile
    }

    // ---- rowsum reduction: quad lanes, then the two kg warps per rowgroup ----
    rs0 += __shfl_xor_sync(0xFFFFFFFFu, rs0, 1);
    rs0 += __shfl_xor_sync(0xFFFFFFFFu, rs0, 2);
    rs1 += __shfl_xor_sync(0xFFFFFFFFu, rs1, 1);
    rs1 += __shfl_xor_sync(0xFFFFFFFFu, rs1, 2);
    if (qc == 0) {
        atomicAdd(&RowRed[r0], rs0);
        atomicAdd(&RowRed[r0 + 8], rs1);
    }
    __syncthreads();
    if (tid < 64) RowRed[tid] = 1.0f / RowRed[tid];
    __syncthreads();

    // ---- write O scaled by 1/rowsum ----
    {
        float inv0 = RowRed[r0];
        float inv1 = RowRed[r0 + 8];
#pragma unroll
        for (int nt = 0; nt < 4; nt++) {
            int dcol = kg * 32 + nt * 8 + 2 * qc;
            size_t oi = ((size_t)(bb * TQ_ + qbase + r0)) * D_ + dcol;
            *(float2*)(out + oi) =
                make_float2(oacc[nt][0] * inv0, oacc[nt][1] * inv0);
            *(float2*)(out + oi + (size_t)8 * D_) =
                make_float2(oacc[nt][2] * inv1, oacc[nt][3] * inv1);
        }
    }

    // ---- in-place normalize of this CTA's attn slice (mostly L2 hits) ----
    // 64 rows x 512 float4 = 32768 float4, 128 per thread.
#pragma unroll 4
    for (int i = tid; i < 64 * 512; i += 256) {
        int r = i >> 9, cc = i & 511;
        float inv = RowRed[r];
        float4* p = (float4*)(arow + (size_t)r * TK_) + cc;
        float4 x = *p;
        x.x *= inv; x.y *= inv; x.z *= inv; x.w *= inv;
        *p = x;
    }
}

extern "C" void kernel_launch(void* const* d_in, const int* in_sizes, int n_in,
                              void* d_out, int out_size) {
    const float* q = (const float*)d_in[0];
    const float* k = (const float*)d_in[1];
    const float* v = (const float*)d_in[2];
    const unsigned char* mask = (const unsigned char*)d_in[3];

    float* out = (float*)d_out;                       // [B, TQ, D]
    float* attn = out + (size_t)B_ * TQ_ * D_;        // [B, TQ, TK]

    detect_mask_kind<<<1, 256>>>(mask);

    dim3 grid(TQ_ / 64, B_);
    attn_fused<<<grid, 256>>>(q, k, v, mask, out, attn);
}

// round 6
// speedup vs baseline: 1.1437x; 1.0936x over previous
#include <cuda_runtime.h>
#include <cuda_bf16.h>
#include <cstdint>

#define B_   64
#define TQ_  2048
#define TK_  2048
#define D_   64
#define STRW 68   // words per smem row (64 + 4 pad: conflict-free quad access)

// Mask element kind: 1 = 1-byte elements (bool/uint8), 0 = 4-byte (int32/float32)
__device__ int g_mask_kind;

__global__ void detect_mask_kind(const unsigned char* __restrict__ m) {
    __shared__ int flag;
    int tid = threadIdx.x;
    if (tid == 0) flag = 0;
    __syncthreads();
    const uint4* m4 = (const uint4*)m;
    uint4 u = m4[tid];  // 256 threads * 16B = 4096 bytes
    unsigned w[4] = {u.x, u.y, u.z, u.w};
    int bad = 0;
#pragma unroll
    for (int i = 0; i < 4; i++) {
        unsigned x = w[i];
        if (!(x == 0u || x == 1u || x == 0x3F800000u)) bad = 1;
    }
    if (bad) atomicOr(&flag, 1);
    __syncthreads();
    if (tid == 0) g_mask_kind = flag ? 1 : 0;
}

// fast exp(s/8) via exp2: 5th-order poly, rel err ~3e-6.
__device__ __forceinline__ float fexp8(float s) {
    const float C = 0.18033688011112042f;  // log2(e)/8
    float z = fmaf(s, C, 12582912.0f);
    float nf = z - 12582912.0f;
    float f = fmaf(s, C, -nf);
    int n = __float_as_int(z) - 0x4B400000;
    float p = 1.3333558146e-3f;
    p = fmaf(p, f, 9.6181291076e-3f);
    p = fmaf(p, f, 5.5504108665e-2f);
    p = fmaf(p, f, 2.4022650696e-1f);
    p = fmaf(p, f, 6.9314718056e-1f);
    p = fmaf(p, f, 1.0f);
    return __int_as_float(__float_as_int(p) + (n << 23));
}

__device__ __forceinline__ unsigned cvt_tf32(float x) {
    unsigned r;
    asm("cvt.rna.tf32.f32 %0, %1;" : "=r"(r) : "f"(x));
    return r;
}

__device__ __forceinline__ void mma8(float c[4], const unsigned a[4],
                                     unsigned b0, unsigned b1) {
    asm("mma.sync.aligned.m16n8k8.row.col.f32.tf32.tf32.f32 "
        "{%0,%1,%2,%3}, {%4,%5,%6,%7}, {%8,%9}, {%0,%1,%2,%3};"
        : "+f"(c[0]), "+f"(c[1]), "+f"(c[2]), "+f"(c[3])
        : "r"(a[0]), "r"(a[1]), "r"(a[2]), "r"(a[3]), "r"(b0), "r"(b1));
}

__device__ __forceinline__ void cp16(void* sdst, const void* gsrc) {
    unsigned s = (unsigned)__cvta_generic_to_shared(sdst);
    asm volatile("cp.async.cg.shared.global [%0], [%1], 16;\n" :: "r"(s), "l"(gsrc));
}
__device__ __forceinline__ void cp_commit() {
    asm volatile("cp.async.commit_group;\n");
}
template <int N>
__device__ __forceinline__ void cp_wait() {
    asm volatile("cp.async.wait_group %0;\n" :: "n"(N));
}

// ---------------------------------------------------------------------------
// Fused single pass, cp.async double-buffered.
// CTA: 64 q-rows x full TK. 8 warps: rowgroup wid/2 (16 rows), kg/dg = wid&1.
// ---------------------------------------------------------------------------
__global__ __launch_bounds__(256, 2)
void attn_fused(const float* __restrict__ q, const float* __restrict__ k,
                const float* __restrict__ v, const unsigned char* __restrict__ mask,
                float* __restrict__ out, float* __restrict__ attn) {
    extern __shared__ __align__(16) unsigned char smemraw[];
    float* Kb = (float*)smemraw;                       // [2][64][STRW] raw f32 K
    float* Vb = Kb + 2 * 64 * STRW;                    // [64][STRW]    raw f32 V
    float* Psb = Vb + 64 * STRW;                       // [64][STRW]    f32 e (Q @init)
    unsigned char* Msb = (unsigned char*)(Psb + 64 * STRW);  // [2][64*80]
    float* RowRed = (float*)(Msb + 2 * 64 * 80);       // [64]

#define KS(st, r, c) Kb[(st) * (64 * STRW) + (r) * STRW + (c)]
#define VS(r, c)     Vb[(r) * STRW + (c)]
#define PS(r, c)     Psb[(r) * STRW + (c)]
#define MS(st, i)    Msb[(st) * (64 * 80) + (i)]

    const int tid = threadIdx.x;
    const int wid = tid >> 5;
    const int lane = tid & 31;
    const int bb = blockIdx.y;
    const int qbase = blockIdx.x * 64;

    const float* qp = q + ((size_t)bb * TQ_ + qbase) * D_;
    const float* kp = k + (size_t)bb * TK_ * D_;
    const float* vp = v + (size_t)bb * TK_ * D_;
    float* arow = attn + ((size_t)bb * TQ_ + qbase) * TK_;
    const size_t mbase = ((size_t)bb * TQ_ + qbase) * TK_;
    const int mask_is_byte = g_mask_kind;

    if (tid < 64) RowRed[tid] = 0.0f;

    // Per-thread staging coords: 4 chunks of 16B covering a 64x64 f32 tile
    const int sr = tid >> 4;            // row for chunk j: sr + (j<<4)? no:
    // i = tid + j*256 -> r = i>>4, c4 = (i&15)*4. tid>>4 in 0..15, so
    // r = (tid>>4) + j*16, c4 = (tid&15)*4.
    const int rr = tid >> 4;
    const int c4 = (tid & 15) * 4;
    (void)sr;

    // mask staging coords (byte case): 1 chunk of 16B per thread
    const int mr = tid >> 2;
    const int mseg = (tid & 3) * 16;

    // ---- prologue: prefetch K(0), mask(0); stage Q synchronously ----
#pragma unroll
    for (int j = 0; j < 4; j++)
        cp16(&KS(0, rr + j * 16, c4), kp + (size_t)(rr + j * 16) * D_ + c4);
    if (mask_is_byte) {
        cp16(&MS(0, mr * 80 + mseg), mask + mbase + (size_t)mr * TK_ + mseg);
    } else {
        const int* mi = (const int*)mask;
#pragma unroll
        for (int j = 0; j < 4; j++) {
            int r = rr + j * 16;
            int4 mm = *(const int4*)(mi + mbase + (size_t)r * TK_ + c4);
            uchar4 pk;
            pk.x = mm.x ? 1 : 0; pk.y = mm.y ? 1 : 0;
            pk.z = mm.z ? 1 : 0; pk.w = mm.w ? 1 : 0;
            *(uchar4*)&MS(0, r * 80 + c4) = pk;
        }
    }
    cp_commit();

    // Q -> Psb (raw f32), then to registers as tf32 fragments
#pragma unroll
    for (int j = 0; j < 4; j++)
        *(float4*)&PS(rr + j * 16, c4) = *(const float4*)(qp + (rr + j * 16) * D_ + c4);
    __syncthreads();

    const int rg = wid >> 1;
    const int kg = wid & 1;
    const int r0 = rg * 16 + (lane >> 2);
    const int qc = lane & 3;

    unsigned qa[8][4];
#pragma unroll
    for (int kc = 0; kc < 8; kc++) {
        qa[kc][0] = cvt_tf32(PS(r0, kc * 8 + qc));
        qa[kc][1] = cvt_tf32(PS(r0 + 8, kc * 8 + qc));
        qa[kc][2] = cvt_tf32(PS(r0, kc * 8 + qc + 4));
        qa[kc][3] = cvt_tf32(PS(r0 + 8, kc * 8 + qc + 4));
    }
    cp_wait<0>();     // K(0)/mask(0) arrived
    __syncthreads();  // qa built; Psb free for e-values; K visible to all

    float oacc[4][4];
#pragma unroll
    for (int nt = 0; nt < 4; nt++)
#pragma unroll
        for (int i = 0; i < 4; i++) oacc[nt][i] = 0.0f;
    float rs0 = 0.0f, rs1 = 0.0f;

    for (int kt = 0; kt < TK_ / 64; kt++) {
        const int kb = kt * 64;
        const int p = kt & 1;

        // --- group 1: V(kt) (Vbuf free: prev PV finished before last sync) ---
#pragma unroll
        for (int j = 0; j < 4; j++)
            cp16(&VS(rr + j * 16, c4), vp + (size_t)(kb + rr + j * 16) * D_ + c4);
        cp_commit();

        // --- group 2: K(kt+1) + mask(kt+1) into buffer p^1 ---
        if (kt + 1 < TK_ / 64) {
            const int kb2 = kb + 64;
#pragma unroll
            for (int j = 0; j < 4; j++)
                cp16(&KS(p ^ 1, rr + j * 16, c4),
                     kp + (size_t)(kb2 + rr + j * 16) * D_ + c4);
            if (mask_is_byte) {
                cp16(&MS(p ^ 1, mr * 80 + mseg),
                     mask + mbase + (size_t)mr * TK_ + kb2 + mseg);
            } else {
                const int* mi = (const int*)mask;
#pragma unroll
                for (int j = 0; j < 4; j++) {
                    int r = rr + j * 16;
                    int4 mm = *(const int4*)(mi + mbase + (size_t)r * TK_ + kb2 + c4);
                    uchar4 pk;
                    pk.x = mm.x ? 1 : 0; pk.y = mm.y ? 1 : 0;
                    pk.z = mm.z ? 1 : 0; pk.w = mm.w ? 1 : 0;
                    *(uchar4*)&MS(p ^ 1, r * 80 + c4) = pk;
                }
            }
        }
        cp_commit();

        // --- S = Q * K^T (B operands: LDS f32 + cvt) ---
        float c[4][4];
#pragma unroll
        for (int nt = 0; nt < 4; nt++)
#pragma unroll
            for (int i = 0; i < 4; i++) c[nt][i] = 0.0f;

#pragma unroll
        for (int kc = 0; kc < 8; kc++) {
#pragma unroll
            for (int nt = 0; nt < 4; nt++) {
                int key = kg * 32 + nt * 8 + (lane >> 2);
                unsigned b0 = cvt_tf32(KS(p, key, kc * 8 + qc));
                unsigned b1 = cvt_tf32(KS(p, key, kc * 8 + qc + 4));
                mma8(c[nt], qa[kc], b0, b1);
            }
        }

        // --- mask + exp -> Psb (f32), rowsum in regs ---
#pragma unroll
        for (int nt = 0; nt < 4; nt++) {
            int col = kg * 32 + nt * 8 + 2 * qc;
            float e00 = MS(p, r0 * 80 + col)           ? 0.0f : fexp8(c[nt][0]);
            float e01 = MS(p, r0 * 80 + col + 1)       ? 0.0f : fexp8(c[nt][1]);
            float e10 = MS(p, (r0 + 8) * 80 + col)     ? 0.0f : fexp8(c[nt][2]);
            float e11 = MS(p, (r0 + 8) * 80 + col + 1) ? 0.0f : fexp8(c[nt][3]);
            *(float2*)&PS(r0, col) = make_float2(e00, e01);
            *(float2*)&PS(r0 + 8, col) = make_float2(e10, e11);
            rs0 += e00 + e01;
            rs1 += e10 + e11;
        }

        cp_wait<1>();     // V(kt) arrived (K(kt+1) group may still be in flight)
        __syncthreads();  // Psb complete + V visible

        // --- O += P * V (A: cvt(Ps), B: cvt(V)) ---
#pragma unroll
        for (int kc = 0; kc < 8; kc++) {
            unsigned a[4];
            a[0] = cvt_tf32(PS(r0, kc * 8 + qc));
            a[1] = cvt_tf32(PS(r0 + 8, kc * 8 + qc));
            a[2] = cvt_tf32(PS(r0, kc * 8 + qc + 4));
            a[3] = cvt_tf32(PS(r0 + 8, kc * 8 + qc + 4));
#pragma unroll
            for (int nt = 0; nt < 4; nt++) {
                int dcol = kg * 32 + nt * 8 + (lane >> 2);
                unsigned b0 = cvt_tf32(VS(kc * 8 + qc, dcol));
                unsigned b1 = cvt_tf32(VS(kc * 8 + qc + 4, dcol));
                mma8(oacc[nt], a, b0, b1);
            }
        }

        // --- coalesced attn tile store from Psb (unnormalized e, f32) ---
#pragma unroll
        for (int j = 0; j < 4; j++) {
            int r = rr + j * 16;
            *(float4*)(arow + (size_t)r * TK_ + kb + c4) = *(float4*)&PS(r, c4);
        }

        cp_wait<0>();     // K(kt+1)/mask(kt+1) arrived
        __syncthreads();  // all reads of Psb/Vbuf done before next overwrite
    }

    // ---- rowsum reduction: quad lanes, then the two kg warps per rowgroup ----
    rs0 += __shfl_xor_sync(0xFFFFFFFFu, rs0, 1);
    rs0 += __shfl_xor_sync(0xFFFFFFFFu, rs0, 2);
    rs1 += __shfl_xor_sync(0xFFFFFFFFu, rs1, 1);
    rs1 += __shfl_xor_sync(0xFFFFFFFFu, rs1, 2);
    if (qc == 0) {
        atomicAdd(&RowRed[r0], rs0);
        atomicAdd(&RowRed[r0 + 8], rs1);
    }
    __syncthreads();
    if (tid < 64) RowRed[tid] = 1.0f / RowRed[tid];
    __syncthreads();

    // ---- write O scaled by 1/rowsum ----
    {
        float inv0 = RowRed[r0];
        float inv1 = RowRed[r0 + 8];
#pragma unroll
        for (int nt = 0; nt < 4; nt++) {
            int dcol = kg * 32 + nt * 8 + 2 * qc;
            size_t oi = ((size_t)(bb * TQ_ + qbase + r0)) * D_ + dcol;
            *(float2*)(out + oi) =
                make_float2(oacc[nt][0] * inv0, oacc[nt][1] * inv0);
            *(float2*)(out + oi + (size_t)8 * D_) =
                make_float2(oacc[nt][2] * inv1, oacc[nt][3] * inv1);
        }
    }

    // ---- in-place normalize of this CTA's attn slice (mostly L2 hits) ----
#pragma unroll 4
    for (int i = tid; i < 64 * 512; i += 256) {
        int r = i >> 9, cc = i & 511;
        float inv = RowRed[r];
        float4* p4 = (float4*)(arow + (size_t)r * TK_) + cc;
        float4 x = *p4;
        x.x *= inv; x.y *= inv; x.z *= inv; x.w *= inv;
        *p4 = x;
    }
}

static const int kSmemBytes = (4 * 64 * STRW) * 4 + 2 * 64 * 80 + 64 * 4;  // 80128

extern "C" void kernel_launch(void* const* d_in, const int* in_sizes, int n_in,
                              void* d_out, int out_size) {
    const float* q = (const float*)d_in[0];
    const float* k = (const float*)d_in[1];
    const float* v = (const float*)d_in[2];
    const unsigned char* mask = (const unsigned char*)d_in[3];

    float* out = (float*)d_out;                 // [B, TQ, D]
    float* attn = out + (size_t)B_ * TQ_ * D_;  // [B, TQ, TK]

    cudaFuncSetAttribute(attn_fused, cudaFuncAttributeMaxDynamicSharedMemorySize,
                         kSmemBytes);

    detect_mask_kind<<<1, 256>>>(mask);

    dim3 grid(TQ_ / 64, B_);
    attn_fused<<<grid, 256, kSmemBytes>>>(q, k, v, mask, out, attn);
}

// round 7
// speedup vs baseline: 1.2093x; 1.0573x over previous
#include <cuda_runtime.h>
#include <cuda_bf16.h>
#include <cstdint>

#define B_   64
#define TQ_  2048
#define TK_  2048
#define D_   64
#define STRW 68     // words per smem row (64 + 4 pad: conflict-free quad access)
#define MROWS 128   // q-rows per CTA
#define NT_  (TK_ / 64)

// Mask element kind: 1 = 1-byte elements (bool/uint8), 0 = 4-byte (int32/float32)
__device__ int g_mask_kind;

__global__ void detect_mask_kind(const unsigned char* __restrict__ m) {
    __shared__ int flag;
    int tid = threadIdx.x;
    if (tid == 0) flag = 0;
    __syncthreads();
    const uint4* m4 = (const uint4*)m;
    uint4 u = m4[tid];  // 256 threads * 16B = 4096 bytes
    unsigned w[4] = {u.x, u.y, u.z, u.w};
    int bad = 0;
#pragma unroll
    for (int i = 0; i < 4; i++) {
        unsigned x = w[i];
        if (!(x == 0u || x == 1u || x == 0x3F800000u)) bad = 1;
    }
    if (bad) atomicOr(&flag, 1);
    __syncthreads();
    if (tid == 0) g_mask_kind = flag ? 1 : 0;
}

// fast exp(s/8) via exp2: 5th-order poly, rel err ~3e-6.
__device__ __forceinline__ float fexp8(float s) {
    const float C = 0.18033688011112042f;  // log2(e)/8
    float z = fmaf(s, C, 12582912.0f);
    float nf = z - 12582912.0f;
    float f = fmaf(s, C, -nf);
    int n = __float_as_int(z) - 0x4B400000;
    float p = 1.3333558146e-3f;
    p = fmaf(p, f, 9.6181291076e-3f);
    p = fmaf(p, f, 5.5504108665e-2f);
    p = fmaf(p, f, 2.4022650696e-1f);
    p = fmaf(p, f, 6.9314718056e-1f);
    p = fmaf(p, f, 1.0f);
    return __int_as_float(__float_as_int(p) + (n << 23));
}

__device__ __forceinline__ unsigned cvt_tf32(float x) {
    unsigned r;
    asm("cvt.rna.tf32.f32 %0, %1;" : "=r"(r) : "f"(x));
    return r;
}

__device__ __forceinline__ void mma8(float c[4], const unsigned a[4],
                                     unsigned b0, unsigned b1) {
    asm("mma.sync.aligned.m16n8k8.row.col.f32.tf32.tf32.f32 "
        "{%0,%1,%2,%3}, {%4,%5,%6,%7}, {%8,%9}, {%0,%1,%2,%3};"
        : "+f"(c[0]), "+f"(c[1]), "+f"(c[2]), "+f"(c[3])
        : "r"(a[0]), "r"(a[1]), "r"(a[2]), "r"(a[3]), "r"(b0), "r"(b1));
}

__device__ __forceinline__ void cp16(void* sdst, const void* gsrc) {
    unsigned s = (unsigned)__cvta_generic_to_shared(sdst);
    asm volatile("cp.async.cg.shared.global [%0], [%1], 16;\n" :: "r"(s), "l"(gsrc));
}
__device__ __forceinline__ void cp_commit() {
    asm volatile("cp.async.commit_group;\n");
}
template <int N>
__device__ __forceinline__ void cp_wait() {
    asm volatile("cp.async.wait_group %0;\n" :: "n"(N));
}
__device__ __forceinline__ void bar_pair(int id) {
    asm volatile("bar.sync %0, 64;\n" :: "r"(id) : "memory");
}

// ---------------------------------------------------------------------------
// Fused single pass. CTA: 128 q-rows x full TK, 512 threads / 16 warps.
// rowgroup rg = wid>>1 (16 rows), keygroup/dgroup kg = wid&1 (32 cols).
// Per tile: 1 full sync (K/V/M buffer flip) + 1 pair barrier (Ps handoff).
// K, V, mask all double-buffered, prefetched one tile ahead via cp.async.
// ---------------------------------------------------------------------------
__global__ __launch_bounds__(512, 1)
void attn_fused(const float* __restrict__ q, const float* __restrict__ k,
                const float* __restrict__ v, const unsigned char* __restrict__ mask,
                float* __restrict__ out, float* __restrict__ attn) {
    extern __shared__ __align__(16) unsigned char smemraw[];
    float* Kb = (float*)smemraw;                         // [2][64][STRW] f32 K
    float* Vb = Kb + 2 * 64 * STRW;                      // [2][64][STRW] f32 V
    float* Psb = Vb + 2 * 64 * STRW;                     // [128][STRW] e (Q @init)
    unsigned char* Msb = (unsigned char*)(Psb + MROWS * STRW);  // [2][128*80]
    float* RowRed = (float*)(Msb + 2 * MROWS * 80);      // [128]

#define KS(st, r, c) Kb[(st) * (64 * STRW) + (r) * STRW + (c)]
#define VS(st, r, c) Vb[(st) * (64 * STRW) + (r) * STRW + (c)]
#define PS(r, c)     Psb[(r) * STRW + (c)]
#define MS(st, i)    Msb[(st) * (MROWS * 80) + (i)]

    const int tid = threadIdx.x;
    const int wid = tid >> 5;
    const int lane = tid & 31;
    const int bb = blockIdx.y;
    const int qbase = blockIdx.x * MROWS;

    const float* qp = q + ((size_t)bb * TQ_ + qbase) * D_;
    const float* kp = k + (size_t)bb * TK_ * D_;
    const float* vp = v + (size_t)bb * TK_ * D_;
    float* arow = attn + ((size_t)bb * TQ_ + qbase) * TK_;
    const size_t mbase = ((size_t)bb * TQ_ + qbase) * TK_;
    const int mask_is_byte = g_mask_kind;

    if (tid < MROWS) RowRed[tid] = 0.0f;

    // K/V staging coords: 64x64 f32 tile, 512 threads -> 2 chunks of 16B each
    const int rr = tid >> 4;          // 0..31 ; rows rr, rr+32
    const int c4 = (tid & 15) * 4;
    // byte-mask staging: 128 rows x 64B -> 1 chunk of 16B per thread
    const int mr = tid >> 2;          // 0..127
    const int mseg = (tid & 3) * 16;

    // ---- prologue: prefetch K(0), V(0), mask(0) ----
#pragma unroll
    for (int j = 0; j < 2; j++) {
        cp16(&KS(0, rr + j * 32, c4), kp + (size_t)(rr + j * 32) * D_ + c4);
        cp16(&VS(0, rr + j * 32, c4), vp + (size_t)(rr + j * 32) * D_ + c4);
    }
    if (mask_is_byte) {
        cp16(&MS(0, mr * 80 + mseg), mask + mbase + (size_t)mr * TK_ + mseg);
    } else {
        const int* mi = (const int*)mask;
#pragma unroll
        for (int j = 0; j < 4; j++) {
            int i4 = tid + j * 512;
            int r = i4 >> 4, cc = (i4 & 15) * 4;
            int4 mm = *(const int4*)(mi + mbase + (size_t)r * TK_ + cc);
            uchar4 pk;
            pk.x = mm.x ? 1 : 0; pk.y = mm.y ? 1 : 0;
            pk.z = mm.z ? 1 : 0; pk.w = mm.w ? 1 : 0;
            *(uchar4*)&MS(0, r * 80 + cc) = pk;
        }
    }
    cp_commit();

    // Stage Q (128x64) into Psb (raw f32), then to tf32 A fragments
#pragma unroll
    for (int j = 0; j < 4; j++) {
        int r = rr + j * 32;
        *(float4*)&PS(r, c4) = *(const float4*)(qp + r * D_ + c4);
    }
    __syncthreads();

    const int rg = wid >> 1;                 // 0..7
    const int kg = wid & 1;
    const int r0 = rg * 16 + (lane >> 2);    // 0..127
    const int qc = lane & 3;

    unsigned qa[8][4];
#pragma unroll
    for (int kc = 0; kc < 8; kc++) {
        qa[kc][0] = cvt_tf32(PS(r0, kc * 8 + qc));
        qa[kc][1] = cvt_tf32(PS(r0 + 8, kc * 8 + qc));
        qa[kc][2] = cvt_tf32(PS(r0, kc * 8 + qc + 4));
        qa[kc][3] = cvt_tf32(PS(r0 + 8, kc * 8 + qc + 4));
    }
    cp_wait<0>();     // K0/V0/M0 arrived
    __syncthreads();  // qa built; Psb free; tiles visible to all

    float oacc[4][4];
#pragma unroll
    for (int nt = 0; nt < 4; nt++)
#pragma unroll
        for (int i = 0; i < 4; i++) oacc[nt][i] = 0.0f;
    float rs0 = 0.0f, rs1 = 0.0f;

    // pair-local index for the attn tile store (64 threads per rowgroup pair)
    const int t64 = kg * 32 + lane;

    for (int kt = 0; kt < NT_; kt++) {
        const int kb = kt * 64;
        const int p = kt & 1;

        // --- prefetch tile kt+1 into buffer p^1 (single group) ---
        if (kt + 1 < NT_) {
            const int kb2 = kb + 64;
#pragma unroll
            for (int j = 0; j < 2; j++) {
                int r = rr + j * 32;
                cp16(&KS(p ^ 1, r, c4), kp + (size_t)(kb2 + r) * D_ + c4);
                cp16(&VS(p ^ 1, r, c4), vp + (size_t)(kb2 + r) * D_ + c4);
            }
            if (mask_is_byte) {
                cp16(&MS(p ^ 1, mr * 80 + mseg),
                     mask + mbase + (size_t)mr * TK_ + kb2 + mseg);
            } else {
                const int* mi = (const int*)mask;
#pragma unroll
                for (int j = 0; j < 4; j++) {
                    int i4 = tid + j * 512;
                    int r = i4 >> 4, cc = (i4 & 15) * 4;
                    int4 mm = *(const int4*)(mi + mbase + (size_t)r * TK_ + kb2 + cc);
                    uchar4 pk;
                    pk.x = mm.x ? 1 : 0; pk.y = mm.y ? 1 : 0;
                    pk.z = mm.z ? 1 : 0; pk.w = mm.w ? 1 : 0;
                    *(uchar4*)&MS(p ^ 1, r * 80 + cc) = pk;
                }
            }
        }
        cp_commit();

        // --- S = Q * K^T for this warp's 16x32 subtile ---
        float c[4][4];
#pragma unroll
        for (int nt = 0; nt < 4; nt++)
#pragma unroll
            for (int i = 0; i < 4; i++) c[nt][i] = 0.0f;

#pragma unroll
        for (int kc = 0; kc < 8; kc++) {
#pragma unroll
            for (int nt = 0; nt < 4; nt++) {
                int key = kg * 32 + nt * 8 + (lane >> 2);
                unsigned b0 = cvt_tf32(KS(p, key, kc * 8 + qc));
                unsigned b1 = cvt_tf32(KS(p, key, kc * 8 + qc + 4));
                mma8(c[nt], qa[kc], b0, b1);
            }
        }

        // --- mask + exp -> Psb (own rows), rowsum in regs ---
#pragma unroll
        for (int nt = 0; nt < 4; nt++) {
            int col = kg * 32 + nt * 8 + 2 * qc;
            float e00 = MS(p, r0 * 80 + col)           ? 0.0f : fexp8(c[nt][0]);
            float e01 = MS(p, r0 * 80 + col + 1)       ? 0.0f : fexp8(c[nt][1]);
            float e10 = MS(p, (r0 + 8) * 80 + col)     ? 0.0f : fexp8(c[nt][2]);
            float e11 = MS(p, (r0 + 8) * 80 + col + 1) ? 0.0f : fexp8(c[nt][3]);
            *(float2*)&PS(r0, col) = make_float2(e00, e01);
            *(float2*)&PS(r0 + 8, col) = make_float2(e10, e11);
            rs0 += e00 + e01;
            rs1 += e10 + e11;
        }

        bar_pair(rg + 1);  // Ps rows of this pair complete

        // --- O += P * V ---
#pragma unroll
        for (int kc = 0; kc < 8; kc++) {
            unsigned a[4];
            a[0] = cvt_tf32(PS(r0, kc * 8 + qc));
            a[1] = cvt_tf32(PS(r0 + 8, kc * 8 + qc));
            a[2] = cvt_tf32(PS(r0, kc * 8 + qc + 4));
            a[3] = cvt_tf32(PS(r0 + 8, kc * 8 + qc + 4));
#pragma unroll
            for (int nt = 0; nt < 4; nt++) {
                int dcol = kg * 32 + nt * 8 + (lane >> 2);
                unsigned b0 = cvt_tf32(VS(p, kc * 8 + qc, dcol));
                unsigned b1 = cvt_tf32(VS(p, kc * 8 + qc + 4, dcol));
                mma8(oacc[nt], a, b0, b1);
            }
        }

        // --- coalesced attn tile store (pair-local rows) ---
#pragma unroll
        for (int j = 0; j < 4; j++) {
            int i = t64 + j * 64;
            int r = rg * 16 + (i >> 4);
            int cc = (i & 15) * 4;
            *(float4*)(arow + (size_t)r * TK_ + kb + cc) = *(float4*)&PS(r, cc);
        }

        cp_wait<0>();     // prefetch(kt+1) landed (had whole tile to fly)
        __syncthreads();  // buffer flip: everyone done with p-buffers & Ps
    }

    // ---- rowsum reduction: quad lanes, then the two kg warps per rowgroup ----
    rs0 += __shfl_xor_sync(0xFFFFFFFFu, rs0, 1);
    rs0 += __shfl_xor_sync(0xFFFFFFFFu, rs0, 2);
    rs1 += __shfl_xor_sync(0xFFFFFFFFu, rs1, 1);
    rs1 += __shfl_xor_sync(0xFFFFFFFFu, rs1, 2);
    if (qc == 0) {
        atomicAdd(&RowRed[r0], rs0);
        atomicAdd(&RowRed[r0 + 8], rs1);
    }
    __syncthreads();
    if (tid < MROWS) RowRed[tid] = 1.0f / RowRed[tid];
    __syncthreads();

    // ---- write O scaled by 1/rowsum ----
    {
        float inv0 = RowRed[r0];
        float inv1 = RowRed[r0 + 8];
#pragma unroll
        for (int nt = 0; nt < 4; nt++) {
            int dcol = kg * 32 + nt * 8 + 2 * qc;
            size_t oi = ((size_t)(bb * TQ_ + qbase + r0)) * D_ + dcol;
            *(float2*)(out + oi) =
                make_float2(oacc[nt][0] * inv0, oacc[nt][1] * inv0);
            *(float2*)(out + oi + (size_t)8 * D_) =
                make_float2(oacc[nt][2] * inv1, oacc[nt][3] * inv1);
        }
    }

    // ---- in-place normalize of this CTA's attn slice (mostly L2 hits) ----
#pragma unroll 4
    for (int i = tid; i < MROWS * 512; i += 512) {
        int r = i >> 9, cc = i & 511;
        float inv = RowRed[r];
        float4* p4 = (float4*)(arow + (size_t)r * TK_) + cc;
        float4 x = *p4;
        x.x *= inv; x.y *= inv; x.z *= inv; x.w *= inv;
        *p4 = x;
    }
}

static const int kSmemBytes =
    (2 * 64 * STRW + 2 * 64 * STRW + MROWS * STRW) * 4 + 2 * MROWS * 80 + MROWS * 4;

extern "C" void kernel_launch(void* const* d_in, const int* in_sizes, int n_in,
                              void* d_out, int out_size) {
    const float* q = (const float*)d_in[0];
    const float* k = (const float*)d_in[1];
    const float* v = (const float*)d_in[2];
    const unsigned char* mask = (const unsigned char*)d_in[3];

    float* out = (float*)d_out;                 // [B, TQ, D]
    float* attn = out + (size_t)B_ * TQ_ * D_;  // [B, TQ, TK]

    cudaFuncSetAttribute(attn_fused, cudaFuncAttributeMaxDynamicSharedMemorySize,
                         kSmemBytes);

    detect_mask_kind<<<1, 256>>>(mask);

    dim3 grid(TQ_ / MROWS, B_);
    attn_fused<<<grid, 512, kSmemBytes>>>(q, k, v, mask, out, attn);
}

// round 8
// speedup vs baseline: 1.2255x; 1.0135x over previous
#include <cuda_runtime.h>
#include <cuda_bf16.h>
#include <cstdint>

#define B_   64
#define TQ_  2048
#define TK_  2048
#define D_   64
#define STRW 68     // words per smem row (64 + 4 pad: conflict-free quad access)
#define MROWS 128   // q-rows per CTA
#define NT_  (TK_ / 64)

// Mask element kind: 1 = 1-byte elements (bool/uint8), 0 = 4-byte (int32/float32)
__device__ int g_mask_kind;

__global__ void detect_mask_kind(const unsigned char* __restrict__ m) {
    __shared__ int flag;
    int tid = threadIdx.x;
    if (tid == 0) flag = 0;
    __syncthreads();
    const uint4* m4 = (const uint4*)m;
    uint4 u = m4[tid];  // 256 threads * 16B = 4096 bytes
    unsigned w[4] = {u.x, u.y, u.z, u.w};
    int bad = 0;
#pragma unroll
    for (int i = 0; i < 4; i++) {
        unsigned x = w[i];
        if (!(x == 0u || x == 1u || x == 0x3F800000u)) bad = 1;
    }
    if (bad) atomicOr(&flag, 1);
    __syncthreads();
    if (tid == 0) g_mask_kind = flag ? 1 : 0;
}

// fast exp(s/8) via exp2: 5th-order poly, rel err ~3e-6.
__device__ __forceinline__ float fexp8(float s) {
    const float C = 0.18033688011112042f;  // log2(e)/8
    float z = fmaf(s, C, 12582912.0f);
    float nf = z - 12582912.0f;
    float f = fmaf(s, C, -nf);
    int n = __float_as_int(z) - 0x4B400000;
    float p = 1.3333558146e-3f;
    p = fmaf(p, f, 9.6181291076e-3f);
    p = fmaf(p, f, 5.5504108665e-2f);
    p = fmaf(p, f, 2.4022650696e-1f);
    p = fmaf(p, f, 6.9314718056e-1f);
    p = fmaf(p, f, 1.0f);
    return __int_as_float(__float_as_int(p) + (n << 23));
}

__device__ __forceinline__ unsigned cvt_tf32(float x) {
    unsigned r;
    asm("cvt.rna.tf32.f32 %0, %1;" : "=r"(r) : "f"(x));
    return r;
}

__device__ __forceinline__ void mma8(float c[4], const unsigned a[4],
                                     unsigned b0, unsigned b1) {
    asm("mma.sync.aligned.m16n8k8.row.col.f32.tf32.tf32.f32 "
        "{%0,%1,%2,%3}, {%4,%5,%6,%7}, {%8,%9}, {%0,%1,%2,%3};"
        : "+f"(c[0]), "+f"(c[1]), "+f"(c[2]), "+f"(c[3])
        : "r"(a[0]), "r"(a[1]), "r"(a[2]), "r"(a[3]), "r"(b0), "r"(b1));
}

__device__ __forceinline__ void cp16(void* sdst, const void* gsrc) {
    unsigned s = (unsigned)__cvta_generic_to_shared(sdst);
    asm volatile("cp.async.cg.shared.global [%0], [%1], 16;\n" :: "r"(s), "l"(gsrc));
}
__device__ __forceinline__ void cp_commit() {
    asm volatile("cp.async.commit_group;\n");
}
template <int N>
__device__ __forceinline__ void cp_wait() {
    asm volatile("cp.async.wait_group %0;\n" :: "n"(N));
}

// ---------------------------------------------------------------------------
// Fused single pass, deferred-PV pipeline. CTA: 128 q-rows x full TK,
// 512 threads / 16 warps. rowgroup rg = wid>>1 (16 rows), kg = wid&1.
// Tile kt: QK(kt)+exp(kt)->Ps[cur]; PV(kt-1)+attn store(kt-1) from
// Ps[cur^1]/V[(kt-1)&1]. ONE __syncthreads per tile, no pair barriers —
// the cross-warp P handoff rides the previous tile's sync.
// ---------------------------------------------------------------------------
__global__ __launch_bounds__(512, 1)
void attn_fused(const float* __restrict__ q, const float* __restrict__ k,
                const float* __restrict__ v, const unsigned char* __restrict__ mask,
                float* __restrict__ out, float* __restrict__ attn) {
    extern __shared__ __align__(16) unsigned char smemraw[];
    float* Kb = (float*)smemraw;                         // [2][64][STRW] f32 K
    float* Vb = Kb + 2 * 64 * STRW;                      // [2][64][STRW] f32 V
    float* Psb = Vb + 2 * 64 * STRW;                     // [2][128][STRW] f32 e
    unsigned char* Msb = (unsigned char*)(Psb + 2 * MROWS * STRW);  // [2][128*80]
    float* RowRed = (float*)(Msb + 2 * MROWS * 80);      // [128]

#define KS(st, r, c) Kb[(st) * (64 * STRW) + (r) * STRW + (c)]
#define VS(st, r, c) Vb[(st) * (64 * STRW) + (r) * STRW + (c)]
#define PS(st, r, c) Psb[(st) * (MROWS * STRW) + (r) * STRW + (c)]
#define MS(st, i)    Msb[(st) * (MROWS * 80) + (i)]

    const int tid = threadIdx.x;
    const int wid = tid >> 5;
    const int lane = tid & 31;
    const int bb = blockIdx.y;
    const int qbase = blockIdx.x * MROWS;

    const float* qp = q + ((size_t)bb * TQ_ + qbase) * D_;
    const float* kp = k + (size_t)bb * TK_ * D_;
    const float* vp = v + (size_t)bb * TK_ * D_;
    float* arow = attn + ((size_t)bb * TQ_ + qbase) * TK_;
    const size_t mbase = ((size_t)bb * TQ_ + qbase) * TK_;
    const int mask_is_byte = g_mask_kind;

    if (tid < MROWS) RowRed[tid] = 0.0f;

    // K/V staging coords: 64x64 f32 tile, 512 threads -> 2 chunks of 16B each
    const int rr = tid >> 4;          // 0..31 ; rows rr, rr+32
    const int c4 = (tid & 15) * 4;
    // byte-mask staging: 128 rows x 64B -> 1 chunk of 16B per thread
    const int mr = tid >> 2;          // 0..127
    const int mseg = (tid & 3) * 16;

    // ---- prologue: prefetch K(0), mask(0) ----
#pragma unroll
    for (int j = 0; j < 2; j++)
        cp16(&KS(0, rr + j * 32, c4), kp + (size_t)(rr + j * 32) * D_ + c4);
    if (mask_is_byte) {
        cp16(&MS(0, mr * 80 + mseg), mask + mbase + (size_t)mr * TK_ + mseg);
    } else {
        const int* mi = (const int*)mask;
#pragma unroll
        for (int j = 0; j < 4; j++) {
            int i4 = tid + j * 512;
            int r = i4 >> 4, cc = (i4 & 15) * 4;
            int4 mm = *(const int4*)(mi + mbase + (size_t)r * TK_ + cc);
            uchar4 pk;
            pk.x = mm.x ? 1 : 0; pk.y = mm.y ? 1 : 0;
            pk.z = mm.z ? 1 : 0; pk.w = mm.w ? 1 : 0;
            *(uchar4*)&MS(0, r * 80 + cc) = pk;
        }
    }
    cp_commit();

    // Stage Q (128x64) into Ps[0] (raw f32), then to tf32 A fragments
#pragma unroll
    for (int j = 0; j < 4; j++) {
        int r = rr + j * 32;
        *(float4*)&PS(0, r, c4) = *(const float4*)(qp + r * D_ + c4);
    }
    __syncthreads();

    const int rg = wid >> 1;                 // 0..7
    const int kg = wid & 1;
    const int r0 = rg * 16 + (lane >> 2);    // 0..127
    const int qc = lane & 3;

    unsigned qa[8][4];
#pragma unroll
    for (int kc = 0; kc < 8; kc++) {
        qa[kc][0] = cvt_tf32(PS(0, r0, kc * 8 + qc));
        qa[kc][1] = cvt_tf32(PS(0, r0 + 8, kc * 8 + qc));
        qa[kc][2] = cvt_tf32(PS(0, r0, kc * 8 + qc + 4));
        qa[kc][3] = cvt_tf32(PS(0, r0 + 8, kc * 8 + qc + 4));
    }
    cp_wait<0>();     // K0/M0 arrived
    __syncthreads();  // qa built; Ps[0] free; K tile visible to all

    float oacc[4][4];
#pragma unroll
    for (int nt = 0; nt < 4; nt++)
#pragma unroll
        for (int i = 0; i < 4; i++) oacc[nt][i] = 0.0f;
    float rs0 = 0.0f, rs1 = 0.0f;

    for (int kt = 0; kt < NT_; kt++) {
        const int kb = kt * 64;
        const int cur = kt & 1;
        const int prv = cur ^ 1;

        // --- prefetch: V(kt) -> Vb[cur]; K(kt+1)+mask(kt+1) -> [cur^1] ---
#pragma unroll
        for (int j = 0; j < 2; j++) {
            int r = rr + j * 32;
            cp16(&VS(cur, r, c4), vp + (size_t)(kb + r) * D_ + c4);
        }
        if (kt + 1 < NT_) {
            const int kb2 = kb + 64;
#pragma unroll
            for (int j = 0; j < 2; j++) {
                int r = rr + j * 32;
                cp16(&KS(prv, r, c4), kp + (size_t)(kb2 + r) * D_ + c4);
            }
            if (mask_is_byte) {
                cp16(&MS(prv, mr * 80 + mseg),
                     mask + mbase + (size_t)mr * TK_ + kb2 + mseg);
            } else {
                const int* mi = (const int*)mask;
#pragma unroll
                for (int j = 0; j < 4; j++) {
                    int i4 = tid + j * 512;
                    int r = i4 >> 4, cc = (i4 & 15) * 4;
                    int4 mm = *(const int4*)(mi + mbase + (size_t)r * TK_ + kb2 + cc);
                    uchar4 pk;
                    pk.x = mm.x ? 1 : 0; pk.y = mm.y ? 1 : 0;
                    pk.z = mm.z ? 1 : 0; pk.w = mm.w ? 1 : 0;
                    *(uchar4*)&MS(prv, r * 80 + cc) = pk;
                }
            }
        }
        cp_commit();

        // --- S = Q * K^T for this warp's 16x32 subtile (tile kt) ---
        float c[4][4];
#pragma unroll
        for (int nt = 0; nt < 4; nt++)
#pragma unroll
            for (int i = 0; i < 4; i++) c[nt][i] = 0.0f;

#pragma unroll
        for (int kc = 0; kc < 8; kc++) {
#pragma unroll
            for (int nt = 0; nt < 4; nt++) {
                int key = kg * 32 + nt * 8 + (lane >> 2);
                unsigned b0 = cvt_tf32(KS(cur, key, kc * 8 + qc));
                unsigned b1 = cvt_tf32(KS(cur, key, kc * 8 + qc + 4));
                mma8(c[nt], qa[kc], b0, b1);
            }
        }

        // --- mask + exp -> Ps[cur], rowsum in regs ---
#pragma unroll
        for (int nt = 0; nt < 4; nt++) {
            int col = kg * 32 + nt * 8 + 2 * qc;
            float e00 = MS(cur, r0 * 80 + col)           ? 0.0f : fexp8(c[nt][0]);
            float e01 = MS(cur, r0 * 80 + col + 1)       ? 0.0f : fexp8(c[nt][1]);
            float e10 = MS(cur, (r0 + 8) * 80 + col)     ? 0.0f : fexp8(c[nt][2]);
            float e11 = MS(cur, (r0 + 8) * 80 + col + 1) ? 0.0f : fexp8(c[nt][3]);
            *(float2*)&PS(cur, r0, col) = make_float2(e00, e01);
            *(float2*)&PS(cur, r0 + 8, col) = make_float2(e10, e11);
            rs0 += e00 + e01;
            rs1 += e10 + e11;
        }

        // --- deferred: PV(kt-1) + attn store(kt-1) from Ps[prv]/V[prv] ---
        if (kt > 0) {
#pragma unroll
            for (int kc = 0; kc < 8; kc++) {
                unsigned a[4];
                a[0] = cvt_tf32(PS(prv, r0, kc * 8 + qc));
                a[1] = cvt_tf32(PS(prv, r0 + 8, kc * 8 + qc));
                a[2] = cvt_tf32(PS(prv, r0, kc * 8 + qc + 4));
                a[3] = cvt_tf32(PS(prv, r0 + 8, kc * 8 + qc + 4));
#pragma unroll
                for (int nt = 0; nt < 4; nt++) {
                    int dcol = kg * 32 + nt * 8 + (lane >> 2);
                    unsigned b0 = cvt_tf32(VS(prv, kc * 8 + qc, dcol));
                    unsigned b1 = cvt_tf32(VS(prv, kc * 8 + qc + 4, dcol));
                    mma8(oacc[nt], a, b0, b1);
                }
            }
#pragma unroll
            for (int j = 0; j < 4; j++) {
                int i = tid + j * 512;
                int r = i >> 4, cc = (i & 15) * 4;
                *(float4*)(arow + (size_t)r * TK_ + (kb - 64) + cc) =
                    *(float4*)&PS(prv, r, cc);
            }
        }

        cp_wait<0>();     // V(kt), K(kt+1), mask(kt+1) landed
        __syncthreads();  // publishes Ps[cur]; guards all buffer reuse
    }

    // ---- flush: PV + attn store for the last tile ----
    {
        const int lst = (NT_ - 1) & 1;
        const int kb = (NT_ - 1) * 64;
#pragma unroll
        for (int kc = 0; kc < 8; kc++) {
            unsigned a[4];
            a[0] = cvt_tf32(PS(lst, r0, kc * 8 + qc));
            a[1] = cvt_tf32(PS(lst, r0 + 8, kc * 8 + qc));
            a[2] = cvt_tf32(PS(lst, r0, kc * 8 + qc + 4));
            a[3] = cvt_tf32(PS(lst, r0 + 8, kc * 8 + qc + 4));
#pragma unroll
            for (int nt = 0; nt < 4; nt++) {
                int dcol = kg * 32 + nt * 8 + (lane >> 2);
                unsigned b0 = cvt_tf32(VS(lst, kc * 8 + qc, dcol));
                unsigned b1 = cvt_tf32(VS(lst, kc * 8 + qc + 4, dcol));
                mma8(oacc[nt], a, b0, b1);
            }
        }
#pragma unroll
        for (int j = 0; j < 4; j++) {
            int i = tid + j * 512;
            int r = i >> 4, cc = (i & 15) * 4;
            *(float4*)(arow + (size_t)r * TK_ + kb + cc) = *(float4*)&PS(lst, r, cc);
        }
    }

    // ---- rowsum reduction: quad lanes, then the two kg warps per rowgroup ----
    rs0 += __shfl_xor_sync(0xFFFFFFFFu, rs0, 1);
    rs0 += __shfl_xor_sync(0xFFFFFFFFu, rs0, 2);
    rs1 += __shfl_xor_sync(0xFFFFFFFFu, rs1, 1);
    rs1 += __shfl_xor_sync(0xFFFFFFFFu, rs1, 2);
    if (qc == 0) {
        atomicAdd(&RowRed[r0], rs0);
        atomicAdd(&RowRed[r0 + 8], rs1);
    }
    __syncthreads();
    if (tid < MROWS) RowRed[tid] = 1.0f / RowRed[tid];
    __syncthreads();

    // ---- write O scaled by 1/rowsum ----
    {
        float inv0 = RowRed[r0];
        float inv1 = RowRed[r0 + 8];
#pragma unroll
        for (int nt = 0; nt < 4; nt++) {
            int dcol = kg * 32 + nt * 8 + 2 * qc;
            size_t oi = ((size_t)(bb * TQ_ + qbase + r0)) * D_ + dcol;
            *(float2*)(out + oi) =
                make_float2(oacc[nt][0] * inv0, oacc[nt][1] * inv0);
            *(float2*)(out + oi + (size_t)8 * D_) =
                make_float2(oacc[nt][2] * inv1, oacc[nt][3] * inv1);
        }
    }

    // ---- in-place normalize of this CTA's attn slice ----
#pragma unroll 4
    for (int i = tid; i < MROWS * 512; i += 512) {
        int r = i >> 9, cc = i & 511;
        float inv = RowRed[r];
        float4* p4 = (float4*)(arow + (size_t)r * TK_) + cc;
        float4 x = *p4;
        x.x *= inv; x.y *= inv; x.z *= inv; x.w *= inv;
        *p4 = x;
    }
}

static const int kSmemBytes =
    (2 * 64 * STRW + 2 * 64 * STRW + 2 * MROWS * STRW) * 4 + 2 * MROWS * 80 + MROWS * 4;

extern "C" void kernel_launch(void* const* d_in, const int* in_sizes, int n_in,
                              void* d_out, int out_size) {
    const float* q = (const float*)d_in[0];
    const float* k = (const float*)d_in[1];
    const float* v = (const float*)d_in[2];
    const unsigned char* mask = (const unsigned char*)d_in[3];

    float* out = (float*)d_out;                 // [B, TQ, D]
    float* attn = out + (size_t)B_ * TQ_ * D_;  // [B, TQ, TK]

    cudaFuncSetAttribute(attn_fused, cudaFuncAttributeMaxDynamicSharedMemorySize,
                         kSmemBytes);

    detect_mask_kind<<<1, 256>>>(mask);

    dim3 grid(TQ_ / MROWS, B_);
    attn_fused<<<grid, 512, kSmemBytes>>>(q, k, v, mask, out, attn);
}

// round 9
// speedup vs baseline: 1.2312x; 1.0046x over previous
#include <cuda_runtime.h>
#include <cuda_bf16.h>
#include <cstdint>

#define B_   64
#define TQ_  2048
#define TK_  2048
#define D_   64
#define STRW 68     // words per smem row (64 + 4 pad: conflict-free quad access)
#define MROWS 128   // q-rows per CTA
#define NT_  (TK_ / 64)

// Mask element kind: 1 = 1-byte elements (bool/uint8), 0 = 4-byte (int32/float32)
__device__ int g_mask_kind;

__global__ void detect_mask_kind(const unsigned char* __restrict__ m) {
    __shared__ int flag;
    int tid = threadIdx.x;
    if (tid == 0) flag = 0;
    __syncthreads();
    const uint4* m4 = (const uint4*)m;
    uint4 u = m4[tid];  // 256 threads * 16B = 4096 bytes
    unsigned w[4] = {u.x, u.y, u.z, u.w};
    int bad = 0;
#pragma unroll
    for (int i = 0; i < 4; i++) {
        unsigned x = w[i];
        if (!(x == 0u || x == 1u || x == 0x3F800000u)) bad = 1;
    }
    if (bad) atomicOr(&flag, 1);
    __syncthreads();
    if (tid == 0) g_mask_kind = flag ? 1 : 0;
}

// fast exp(s/8) via exp2: 5th-order poly, rel err ~3e-6.
__device__ __forceinline__ float fexp8(float s) {
    const float C = 0.18033688011112042f;  // log2(e)/8
    float z = fmaf(s, C, 12582912.0f);
    float nf = z - 12582912.0f;
    float f = fmaf(s, C, -nf);
    int n = __float_as_int(z) - 0x4B400000;
    float p = 1.3333558146e-3f;
    p = fmaf(p, f, 9.6181291076e-3f);
    p = fmaf(p, f, 5.5504108665e-2f);
    p = fmaf(p, f, 2.4022650696e-1f);
    p = fmaf(p, f, 6.9314718056e-1f);
    p = fmaf(p, f, 1.0f);
    return __int_as_float(__float_as_int(p) + (n << 23));
}

__device__ __forceinline__ unsigned cvt_tf32(float x) {
    unsigned r;
    asm("cvt.rna.tf32.f32 %0, %1;" : "=r"(r) : "f"(x));
    return r;
}

__device__ __forceinline__ void mma8(float c[4], const unsigned a[4],
                                     unsigned b0, unsigned b1) {
    asm("mma.sync.aligned.m16n8k8.row.col.f32.tf32.tf32.f32 "
        "{%0,%1,%2,%3}, {%4,%5,%6,%7}, {%8,%9}, {%0,%1,%2,%3};"
        : "+f"(c[0]), "+f"(c[1]), "+f"(c[2]), "+f"(c[3])
        : "r"(a[0]), "r"(a[1]), "r"(a[2]), "r"(a[3]), "r"(b0), "r"(b1));
}

__device__ __forceinline__ void cp16(void* sdst, const void* gsrc) {
    unsigned s = (unsigned)__cvta_generic_to_shared(sdst);
    asm volatile("cp.async.cg.shared.global [%0], [%1], 16;\n" :: "r"(s), "l"(gsrc));
}
__device__ __forceinline__ void cp_commit() {
    asm volatile("cp.async.commit_group;\n");
}
template <int N>
__device__ __forceinline__ void cp_wait() {
    asm volatile("cp.async.wait_group %0;\n" :: "n"(N));
}

// ---------------------------------------------------------------------------
// Fused single pass, deferred-PV pipeline. CTA: 128 q-rows x full TK,
// 512 threads / 16 warps. rowgroup rg = wid>>1 (16 rows), kg = wid&1.
// Tile kt: QK(kt)+exp(kt)->Ps[cur]; PV(kt-1)+attn store(kt-1) from
// Ps[cur^1]/V[(kt-1)&1]. ONE __syncthreads per tile.
// PV operands (P, V) are fed to mma.tf32 as RAW f32 bits (HW ignores the low
// 13 mantissa bits => RZ-truncated tf32). QK keeps cvt.rna for attn accuracy.
// ---------------------------------------------------------------------------
__global__ __launch_bounds__(512, 1)
void attn_fused(const float* __restrict__ q, const float* __restrict__ k,
                const float* __restrict__ v, const unsigned char* __restrict__ mask,
                float* __restrict__ out, float* __restrict__ attn) {
    extern __shared__ __align__(16) unsigned char smemraw[];
    float* Kb = (float*)smemraw;                         // [2][64][STRW] f32 K
    float* Vb = Kb + 2 * 64 * STRW;                      // [2][64][STRW] f32 V
    float* Psb = Vb + 2 * 64 * STRW;                     // [2][128][STRW] f32 e
    unsigned char* Msb = (unsigned char*)(Psb + 2 * MROWS * STRW);  // [2][128*80]
    float* RowRed = (float*)(Msb + 2 * MROWS * 80);      // [128]

#define KS(st, r, c) Kb[(st) * (64 * STRW) + (r) * STRW + (c)]
#define VS(st, r, c) Vb[(st) * (64 * STRW) + (r) * STRW + (c)]
#define PS(st, r, c) Psb[(st) * (MROWS * STRW) + (r) * STRW + (c)]
#define MS(st, i)    Msb[(st) * (MROWS * 80) + (i)]

    const int tid = threadIdx.x;
    const int wid = tid >> 5;
    const int lane = tid & 31;
    const int bb = blockIdx.y;
    const int qbase = blockIdx.x * MROWS;

    const float* qp = q + ((size_t)bb * TQ_ + qbase) * D_;
    const float* kp = k + (size_t)bb * TK_ * D_;
    const float* vp = v + (size_t)bb * TK_ * D_;
    float* arow = attn + ((size_t)bb * TQ_ + qbase) * TK_;
    const size_t mbase = ((size_t)bb * TQ_ + qbase) * TK_;
    const int mask_is_byte = g_mask_kind;

    if (tid < MROWS) RowRed[tid] = 0.0f;

    // K/V staging coords: 64x64 f32 tile, 512 threads -> 2 chunks of 16B each
    const int rr = tid >> 4;          // 0..31 ; rows rr, rr+32
    const int c4 = (tid & 15) * 4;
    // byte-mask staging: 128 rows x 64B -> 1 chunk of 16B per thread
    const int mr = tid >> 2;          // 0..127
    const int mseg = (tid & 3) * 16;

    // ---- prologue: prefetch K(0), mask(0) ----
#pragma unroll
    for (int j = 0; j < 2; j++)
        cp16(&KS(0, rr + j * 32, c4), kp + (size_t)(rr + j * 32) * D_ + c4);
    if (mask_is_byte) {
        cp16(&MS(0, mr * 80 + mseg), mask + mbase + (size_t)mr * TK_ + mseg);
    } else {
        const int* mi = (const int*)mask;
#pragma unroll
        for (int j = 0; j < 4; j++) {
            int i4 = tid + j * 512;
            int r = i4 >> 4, cc = (i4 & 15) * 4;
            int4 mm = *(const int4*)(mi + mbase + (size_t)r * TK_ + cc);
            uchar4 pk;
            pk.x = mm.x ? 1 : 0; pk.y = mm.y ? 1 : 0;
            pk.z = mm.z ? 1 : 0; pk.w = mm.w ? 1 : 0;
            *(uchar4*)&MS(0, r * 80 + cc) = pk;
        }
    }
    cp_commit();

    // Stage Q (128x64) into Ps[0] (raw f32), then to tf32 A fragments
#pragma unroll
    for (int j = 0; j < 4; j++) {
        int r = rr + j * 32;
        *(float4*)&PS(0, r, c4) = *(const float4*)(qp + r * D_ + c4);
    }
    __syncthreads();

    const int rg = wid >> 1;                 // 0..7
    const int kg = wid & 1;
    const int r0 = rg * 16 + (lane >> 2);    // 0..127
    const int qc = lane & 3;

    unsigned qa[8][4];
#pragma unroll
    for (int kc = 0; kc < 8; kc++) {
        qa[kc][0] = cvt_tf32(PS(0, r0, kc * 8 + qc));
        qa[kc][1] = cvt_tf32(PS(0, r0 + 8, kc * 8 + qc));
        qa[kc][2] = cvt_tf32(PS(0, r0, kc * 8 + qc + 4));
        qa[kc][3] = cvt_tf32(PS(0, r0 + 8, kc * 8 + qc + 4));
    }
    cp_wait<0>();     // K0/M0 arrived
    __syncthreads();  // qa built; Ps[0] free; K tile visible to all

    float oacc[4][4];
#pragma unroll
    for (int nt = 0; nt < 4; nt++)
#pragma unroll
        for (int i = 0; i < 4; i++) oacc[nt][i] = 0.0f;
    float rs0 = 0.0f, rs1 = 0.0f;

    for (int kt = 0; kt < NT_; kt++) {
        const int kb = kt * 64;
        const int cur = kt & 1;
        const int prv = cur ^ 1;

        // --- prefetch: V(kt) -> Vb[cur]; K(kt+1)+mask(kt+1) -> [cur^1] ---
#pragma unroll
        for (int j = 0; j < 2; j++) {
            int r = rr + j * 32;
            cp16(&VS(cur, r, c4), vp + (size_t)(kb + r) * D_ + c4);
        }
        if (kt + 1 < NT_) {
            const int kb2 = kb + 64;
#pragma unroll
            for (int j = 0; j < 2; j++) {
                int r = rr + j * 32;
                cp16(&KS(prv, r, c4), kp + (size_t)(kb2 + r) * D_ + c4);
            }
            if (mask_is_byte) {
                cp16(&MS(prv, mr * 80 + mseg),
                     mask + mbase + (size_t)mr * TK_ + kb2 + mseg);
            } else {
                const int* mi = (const int*)mask;
#pragma unroll
                for (int j = 0; j < 4; j++) {
                    int i4 = tid + j * 512;
                    int r = i4 >> 4, cc = (i4 & 15) * 4;
                    int4 mm = *(const int4*)(mi + mbase + (size_t)r * TK_ + kb2 + cc);
                    uchar4 pk;
                    pk.x = mm.x ? 1 : 0; pk.y = mm.y ? 1 : 0;
                    pk.z = mm.z ? 1 : 0; pk.w = mm.w ? 1 : 0;
                    *(uchar4*)&MS(prv, r * 80 + cc) = pk;
                }
            }
        }
        cp_commit();

        // --- S = Q * K^T for this warp's 16x32 subtile (tile kt) ---
        float c[4][4];
#pragma unroll
        for (int nt = 0; nt < 4; nt++)
#pragma unroll
            for (int i = 0; i < 4; i++) c[nt][i] = 0.0f;

#pragma unroll
        for (int kc = 0; kc < 8; kc++) {
#pragma unroll
            for (int nt = 0; nt < 4; nt++) {
                int key = kg * 32 + nt * 8 + (lane >> 2);
                unsigned b0 = cvt_tf32(KS(cur, key, kc * 8 + qc));
                unsigned b1 = cvt_tf32(KS(cur, key, kc * 8 + qc + 4));
                mma8(c[nt], qa[kc], b0, b1);
            }
        }

        // --- mask + exp -> Ps[cur], rowsum in regs ---
#pragma unroll
        for (int nt = 0; nt < 4; nt++) {
            int col = kg * 32 + nt * 8 + 2 * qc;
            float e00 = MS(cur, r0 * 80 + col)           ? 0.0f : fexp8(c[nt][0]);
            float e01 = MS(cur, r0 * 80 + col + 1)       ? 0.0f : fexp8(c[nt][1]);
            float e10 = MS(cur, (r0 + 8) * 80 + col)     ? 0.0f : fexp8(c[nt][2]);
            float e11 = MS(cur, (r0 + 8) * 80 + col + 1) ? 0.0f : fexp8(c[nt][3]);
            *(float2*)&PS(cur, r0, col) = make_float2(e00, e01);
            *(float2*)&PS(cur, r0 + 8, col) = make_float2(e10, e11);
            rs0 += e00 + e01;
            rs1 += e10 + e11;
        }

        // --- deferred: PV(kt-1) + attn store(kt-1) from Ps[prv]/V[prv] ---
        // P and V fed as raw f32 bits (HW truncates to tf32).
        if (kt > 0) {
#pragma unroll
            for (int kc = 0; kc < 8; kc++) {
                unsigned a[4];
                a[0] = __float_as_uint(PS(prv, r0, kc * 8 + qc));
                a[1] = __float_as_uint(PS(prv, r0 + 8, kc * 8 + qc));
                a[2] = __float_as_uint(PS(prv, r0, kc * 8 + qc + 4));
                a[3] = __float_as_uint(PS(prv, r0 + 8, kc * 8 + qc + 4));
#pragma unroll
                for (int nt = 0; nt < 4; nt++) {
                    int dcol = kg * 32 + nt * 8 + (lane >> 2);
                    unsigned b0 = __float_as_uint(VS(prv, kc * 8 + qc, dcol));
                    unsigned b1 = __float_as_uint(VS(prv, kc * 8 + qc + 4, dcol));
                    mma8(oacc[nt], a, b0, b1);
                }
            }
#pragma unroll
            for (int j = 0; j < 4; j++) {
                int i = tid + j * 512;
                int r = i >> 4, cc = (i & 15) * 4;
                *(float4*)(arow + (size_t)r * TK_ + (kb - 64) + cc) =
                    *(float4*)&PS(prv, r, cc);
            }
        }

        cp_wait<0>();     // V(kt), K(kt+1), mask(kt+1) landed
        __syncthreads();  // publishes Ps[cur]; guards all buffer reuse
    }

    // ---- flush: PV + attn store for the last tile ----
    {
        const int lst = (NT_ - 1) & 1;
        const int kb = (NT_ - 1) * 64;
#pragma unroll
        for (int kc = 0; kc < 8; kc++) {
            unsigned a[4];
            a[0] = __float_as_uint(PS(lst, r0, kc * 8 + qc));
            a[1] = __float_as_uint(PS(lst, r0 + 8, kc * 8 + qc));
            a[2] = __float_as_uint(PS(lst, r0, kc * 8 + qc + 4));
            a[3] = __float_as_uint(PS(lst, r0 + 8, kc * 8 + qc + 4));
#pragma unroll
            for (int nt = 0; nt < 4; nt++) {
                int dcol = kg * 32 + nt * 8 + (lane >> 2);
                unsigned b0 = __float_as_uint(VS(lst, kc * 8 + qc, dcol));
                unsigned b1 = __float_as_uint(VS(lst, kc * 8 + qc + 4, dcol));
                mma8(oacc[nt], a, b0, b1);
            }
        }
#pragma unroll
        for (int j = 0; j < 4; j++) {
            int i = tid + j * 512;
            int r = i >> 4, cc = (i & 15) * 4;
            *(float4*)(arow + (size_t)r * TK_ + kb + cc) = *(float4*)&PS(lst, r, cc);
        }
    }

    // ---- rowsum reduction: quad lanes, then the two kg warps per rowgroup ----
    rs0 += __shfl_xor_sync(0xFFFFFFFFu, rs0, 1);
    rs0 += __shfl_xor_sync(0xFFFFFFFFu, rs0, 2);
    rs1 += __shfl_xor_sync(0xFFFFFFFFu, rs1, 1);
    rs1 += __shfl_xor_sync(0xFFFFFFFFu, rs1, 2);
    if (qc == 0) {
        atomicAdd(&RowRed[r0], rs0);
        atomicAdd(&RowRed[r0 + 8], rs1);
    }
    __syncthreads();
    if (tid < MROWS) RowRed[tid] = 1.0f / RowRed[tid];
    __syncthreads();

    // ---- write O scaled by 1/rowsum ----
    {
        float inv0 = RowRed[r0];
        float inv1 = RowRed[r0 + 8];
#pragma unroll
        for (int nt = 0; nt < 4; nt++) {
            int dcol = kg * 32 + nt * 8 + 2 * qc;
            size_t oi = ((size_t)(bb * TQ_ + qbase + r0)) * D_ + dcol;
            *(float2*)(out + oi) =
                make_float2(oacc[nt][0] * inv0, oacc[nt][1] * inv0);
            *(float2*)(out + oi + (size_t)8 * D_) =
                make_float2(oacc[nt][2] * inv1, oacc[nt][3] * inv1);
        }
    }

    // ---- in-place normalize of this CTA's attn slice ----
#pragma unroll 4
    for (int i = tid; i < MROWS * 512; i += 512) {
        int r = i >> 9, cc = i & 511;
        float inv = RowRed[r];
        float4* p4 = (float4*)(arow + (size_t)r * TK_) + cc;
        float4 x = *p4;
        x.x *= inv; x.y *= inv; x.z *= inv; x.w *= inv;
        *p4 = x;
    }
}

static const int kSmemBytes =
    (2 * 64 * STRW + 2 * 64 * STRW + 2 * MROWS * STRW) * 4 + 2 * MROWS * 80 + MROWS * 4;

extern "C" void kernel_launch(void* const* d_in, const int* in_sizes, int n_in,
                              void* d_out, int out_size) {
    const float* q = (const float*)d_in[0];
    const float* k = (const float*)d_in[1];
    const float* v = (const float*)d_in[2];
    const unsigned char* mask = (const unsigned char*)d_in[3];

    float* out = (float*)d_out;                 // [B, TQ, D]
    float* attn = out + (size_t)B_ * TQ_ * D_;  // [B, TQ, TK]

    cudaFuncSetAttribute(attn_fused, cudaFuncAttributeMaxDynamicSharedMemorySize,
                         kSmemBytes);

    detect_mask_kind<<<1, 256>>>(mask);

    dim3 grid(TQ_ / MROWS, B_);
    attn_fused<<<grid, 512, kSmemBytes>>>(q, k, v, mask, out, attn);
}